// round 12
// baseline (speedup 1.0000x reference)
#include <cuda_runtime.h>
#include <cstddef>

// DPLoss: mean over B rows of [ sum_{j<len[i]} (pred[i,j]-log(align[i,j]))^2 / len[i] ]
// B=4096, T=2048, fp32, len ~ U[1,2048].
//
// R12 = R11 (flat single-wave grid over half-row units + unit/thread-level
// masked-load skipping, ~34MB effective, wall 10.85us) with the unit loop
// unrolled by 2: both units' predicated LDG.128s are issued before either is
// consumed (2x per-warp loads in flight, half the loop overhead). Reg cap 42
// via __launch_bounds__(256,6) keeps theoretical occ at the 75% R11 actually
// achieved.

#define B_ROWS   4096
#define T_COLS   2048
#define T_VEC4   (T_COLS / 4)         // 512 float4 per row
#define NTHREADS 256
#define NCTAS    1184                 // 148 SMs * 8 CTA/SM -> single wave
#define UNITS    (B_ROWS * 2)         // 8192 half-row units

__device__ float    g_acc   = 0.0f;
__device__ unsigned g_count = 0;

// Squared-error contribution of one fully-loaded vec4, scaled by 1/len.
__device__ __forceinline__ float consume(float4 pv, float4 av, int j, int len)
{
    float d0 = pv.x - __logf(av.x);
    float d1 = pv.y - __logf(av.y);
    float d2 = pv.z - __logf(av.z);
    float d3 = pv.w - __logf(av.w);
    float rs;
    if (j + 4 <= len) {                     // fully valid (common case)
        rs = d0 * d0 + d1 * d1 + d2 * d2 + d3 * d3;
    } else {                                // row's last vec4
        rs = d0 * d0;
        if (j + 1 < len) rs += d1 * d1;
        if (j + 2 < len) rs += d2 * d2;
        if (j + 3 < len) rs += d3 * d3;
    }
    return rs * __fdividef(1.0f, (float)len);
}

__global__ __launch_bounds__(NTHREADS, 6) void dploss_kernel(
    const float4* __restrict__ pred,
    const float4* __restrict__ align,
    const int* __restrict__ lens,
    float* __restrict__ out)
{
    const int tid = threadIdx.x;
    float s = 0.0f;

    // 3 unconditional pairs: units bid + k*NCTAS for k = 0..5 (max 5919+1184 < 8192).
    #pragma unroll
    for (int p = 0; p < 3; ++p) {
        const int u0 = blockIdx.x + (2 * p) * NCTAS;
        const int u1 = u0 + NCTAS;

        const int row0 = u0 >> 1, row1 = u1 >> 1;
        const int len0 = __ldg(lens + row0);
        const int len1 = __ldg(lens + row1);

        const int i0 = ((u0 & 1) << 8) | tid;     // vec4 index in row
        const int i1 = ((u1 & 1) << 8) | tid;
        const int j0 = i0 << 2;                   // element index in row
        const int j1 = i1 << 2;

        const bool live0 = (j0 < len0);
        const bool live1 = (j1 < len1);

        float4 pv0, av0, pv1, av1;
        if (live0) {
            const size_t b0 = (size_t)row0 * T_VEC4 + i0;
            pv0 = pred[b0];
            av0 = align[b0];
        }
        if (live1) {
            const size_t b1 = (size_t)row1 * T_VEC4 + i1;
            pv1 = pred[b1];
            av1 = align[b1];
        }

        if (live0) s += consume(pv0, av0, j0, len0);
        if (live1) s += consume(pv1, av1, j1, len1);
    }

    // guarded 7th unit (only CTAs with blockIdx.x < 8192 - 6*1184 = 1088)
    {
        const int u = blockIdx.x + 6 * NCTAS;
        if (u < UNITS) {
            const int row = u >> 1;
            const int len = __ldg(lens + row);
            const int i   = ((u & 1) << 8) | tid;
            const int j   = i << 2;
            if (j < len) {
                const size_t b = (size_t)row * T_VEC4 + i;
                float4 pv = pred[b];
                float4 av = align[b];
                s += consume(pv, av, j, len);
            }
        }
    }

    // warp reduction
    #pragma unroll
    for (int off = 16; off > 0; off >>= 1)
        s += __shfl_down_sync(0xFFFFFFFFu, s, off);

    // block reduction across 8 warps
    __shared__ float warp_sums[NTHREADS / 32];
    const int wid = tid >> 5;
    const int lid = tid & 31;
    if (lid == 0) warp_sums[wid] = s;
    __syncthreads();

    if (wid == 0) {
        float v = (lid < NTHREADS / 32) ? warp_sums[lid] : 0.0f;
        #pragma unroll
        for (int off = 4; off > 0; off >>= 1)
            v += __shfl_down_sync(0xFFFFFFFFu, v, off);

        if (lid == 0) {
            atomicAdd(&g_acc, v);
            __threadfence();
            unsigned prev = atomicInc(&g_count, NCTAS - 1);
            if (prev == NCTAS - 1) {
                float total = atomicExch(&g_acc, 0.0f);   // read + reset for replay
                *out = total * (1.0f / (float)B_ROWS);
            }
        }
    }
}

extern "C" void kernel_launch(void* const* d_in, const int* in_sizes, int n_in,
                              void* d_out, int out_size)
{
    const float4* pred  = (const float4*)d_in[0];
    const float4* align = (const float4*)d_in[1];
    const int*    lens  = (const int*)d_in[2];
    float* out = (float*)d_out;

    dploss_kernel<<<NCTAS, NTHREADS>>>(pred, align, lens, out);
}